// round 9
// baseline (speedup 1.0000x reference)
#include <cuda_runtime.h>

#define BB 2
#define HH 64
#define WW 64
#define CC 128
#define NHEAD 4
#define HD 32
#define KWIN 7
#define MROWS (BB*HH*WW)          /* 8192 */
#define SCALE 0.17677669529663687f /* 32^-0.5 */

// Scratch (allocation-free rule: device globals).
// q/k/v hold tf32 bit patterns (written by GEMM epilogue); att is fp32.
__device__ unsigned g_q[MROWS*CC];
__device__ unsigned g_k[MROWS*CC];
__device__ unsigned g_v[MROWS*CC];
__device__ float    g_att[MROWS*CC];

__device__ __forceinline__ unsigned f2tf(float f) {
    unsigned r;
    asm("cvt.rna.tf32.f32 %0, %1;" : "=r"(r) : "f"(f));
    return r;
}

__device__ __forceinline__ void mma_tf32(float c[4],
    unsigned a0, unsigned a1, unsigned a2, unsigned a3,
    unsigned b0, unsigned b1) {
    asm volatile(
        "mma.sync.aligned.m16n8k8.row.col.f32.tf32.tf32.f32 "
        "{%0,%1,%2,%3}, {%4,%5,%6,%7}, {%8,%9}, {%0,%1,%2,%3};"
        : "+f"(c[0]), "+f"(c[1]), "+f"(c[2]), "+f"(c[3])
        : "r"(a0), "r"(a1), "r"(a2), "r"(a3), "r"(b0), "r"(b1));
}

// ---------------------------------------------------------------------------
// tf32 GEMM v3: 64x64 tile, 128 threads (4 warps = 2M x 2N, warp tile 32x32),
// double-buffered k-chunks of 32. MODE 0 epilogue writes tf32 q/k/v.
// ---------------------------------------------------------------------------
template<int NTOT, int MODE>
__global__ __launch_bounds__(128)
void gemm_tc(const float* __restrict__ A,
             const float* __restrict__ W,
             const float* __restrict__ bias,
             float* __restrict__ out) {
    __shared__ __align__(16) unsigned As[2][64 * 36];
    __shared__ __align__(16) unsigned Bs[2][32 * 72];

    const float* Ap = (MODE == 1) ? (const float*)g_att : A;

    const int tid  = threadIdx.x;
    const int lane = tid & 31;
    const int wid  = tid >> 5;
    const int warpM = wid & 1;
    const int warpN = wid >> 1;
    const int grp = lane >> 2;
    const int tig = lane & 3;
    const int rowbase = blockIdx.x * 64;
    const int colbase = blockIdx.y * 64;

    const int am = tid >> 3;          // 0..15 (+16j)
    const int ak = (tid & 7) * 4;
    const int bk = tid >> 4;          // 0..7 (+8j)
    const int bn = (tid & 15) * 4;

    float4 ra[4], rb[4];

    auto LDG = [&](int kc) {
        const int k0 = kc * 32;
        #pragma unroll
        for (int j = 0; j < 4; ++j)
            ra[j] = *(const float4*)&Ap[(rowbase + am + j * 16) * 128 + k0 + ak];
        #pragma unroll
        for (int j = 0; j < 4; ++j)
            rb[j] = *(const float4*)&W[(k0 + bk + j * 8) * NTOT + colbase + bn];
    };
    auto STS = [&](int buf) {
        #pragma unroll
        for (int j = 0; j < 4; ++j)
            *(uint4*)&As[buf][(am + j * 16) * 36 + ak] =
                make_uint4(f2tf(ra[j].x), f2tf(ra[j].y), f2tf(ra[j].z), f2tf(ra[j].w));
        #pragma unroll
        for (int j = 0; j < 4; ++j)
            *(uint4*)&Bs[buf][(bk + j * 8) * 72 + bn] =
                make_uint4(f2tf(rb[j].x), f2tf(rb[j].y), f2tf(rb[j].z), f2tf(rb[j].w));
    };

    float acc[2][4][4] = {};

    LDG(0);
    STS(0);
    __syncthreads();

    #pragma unroll
    for (int kc = 0; kc < 4; ++kc) {
        if (kc < 3) LDG(kc + 1);
        const int buf = kc & 1;
        #pragma unroll
        for (int ks = 0; ks < 4; ++ks) {
            const int kk = ks * 8;
            unsigned a[2][4], b[4][2];
            #pragma unroll
            for (int mf = 0; mf < 2; ++mf) {
                const int r = warpM * 32 + mf * 16 + grp;
                a[mf][0] = As[buf][r * 36 + kk + tig];
                a[mf][1] = As[buf][(r + 8) * 36 + kk + tig];
                a[mf][2] = As[buf][r * 36 + kk + tig + 4];
                a[mf][3] = As[buf][(r + 8) * 36 + kk + tig + 4];
            }
            #pragma unroll
            for (int nf = 0; nf < 4; ++nf) {
                const int c = warpN * 32 + nf * 8 + grp;
                b[nf][0] = Bs[buf][(kk + tig) * 72 + c];
                b[nf][1] = Bs[buf][(kk + tig + 4) * 72 + c];
            }
            #pragma unroll
            for (int mf = 0; mf < 2; ++mf)
                #pragma unroll
                for (int nf = 0; nf < 4; ++nf)
                    mma_tf32(acc[mf][nf],
                             a[mf][0], a[mf][1], a[mf][2], a[mf][3],
                             b[nf][0], b[nf][1]);
        }
        if (kc < 3) {
            STS((kc + 1) & 1);
            __syncthreads();
        }
    }

    #pragma unroll
    for (int mf = 0; mf < 2; ++mf) {
        #pragma unroll
        for (int nf = 0; nf < 4; ++nf) {
            const int colL = colbase + warpN * 32 + nf * 8 + tig * 2;
            const float bs0 = bias[colL];
            const float bs1 = bias[colL + 1];
            #pragma unroll
            for (int rr = 0; rr < 2; ++rr) {
                const int row = rowbase + warpM * 32 + mf * 16 + grp + rr * 8;
                float v0 = acc[mf][nf][rr * 2 + 0] + bs0;
                float v1 = acc[mf][nf][rr * 2 + 1] + bs1;
                if (MODE == 0) {
                    const int comp  = colL >> 7;
                    const int inner = colL & 127;
                    if (comp == 0)
                        *(uint2*)&g_q[row * CC + inner] = make_uint2(f2tf(v0 * SCALE), f2tf(v1 * SCALE));
                    else if (comp == 1)
                        *(uint2*)&g_k[row * CC + inner] = make_uint2(f2tf(v0), f2tf(v1));
                    else
                        *(uint2*)&g_v[row * CC + inner] = make_uint2(f2tf(v0), f2tf(v1));
                } else {
                    *(float2*)&out[row * NTOT + colL] = make_float2(v0, v1);
                }
            }
        }
    }
}

// ---------------------------------------------------------------------------
// Neighborhood attention v6: 8x8 pixel tile x 1 head = 64 queries = 4 m16
// tiles; warp wid owns m16 tile (pixel rows h0+2wid, h0+2wid+1) x ALL cols.
// Halo 14x14 = 196 px (pad 200) of pre-tf32 K/V in dynamic smem, stride 36.
// Fused per-chunk loop: S-mma -> mask+bias+exp (transient) -> shfl relayout
// -> PV-mma. No barriers after staging; denominator local to warp.
// ---------------------------------------------------------------------------
#define TTH 8
#define TTW 8
#define NHALO_HW 14
#define NPX 196
#define NPAD 200
#define SKSN 36
#define NCHUNK 25
#define NATTEN_DSM (2 * NPAD * SKSN * 4)   /* 57600 bytes */

__global__ __launch_bounds__(128)
void natten_tc(const float* __restrict__ rpb) {
    extern __shared__ __align__(16) unsigned dsm[];
    unsigned* sK = dsm;                 // NPAD*36
    unsigned* sV = dsm + NPAD * SKSN;   // NPAD*36
    __shared__ float srp[169];

    const int tid  = threadIdx.x;
    const int lane = tid & 31;
    const int wid  = tid >> 5;     // 0..3 -> m16 tile
    const int grp  = lane >> 2;    // 0..7
    const int tig  = lane & 3;     // 0..3

    const int w0 = blockIdx.x * TTW;
    const int h0 = blockIdx.y * TTH;
    const int nh = blockIdx.z & 3;
    const int b  = blockIdx.z >> 2;
    const int bbase = b << 12;

    int gh0 = h0 - 3; gh0 = gh0 < 0 ? 0 : (gh0 > 50 ? 50 : gh0);
    int gw0 = w0 - 3; gw0 = gw0 < 0 ? 0 : (gw0 > 50 ? 50 : gw0);

    for (int i = tid; i < 169; i += 128) srp[i] = rpb[nh * 169 + i];

    // Stage K/V halo (already tf32) into stride-36 smem
    const uint4* gk4 = (const uint4*)g_k;
    const uint4* gv4 = (const uint4*)g_v;
    for (int i = tid; i < NPX * 8; i += 128) {
        const int px = i >> 3;
        const int f  = i & 7;
        const int r  = px / NHALO_HW;
        const int c  = px - r * NHALO_HW;
        const int goff = (bbase + ((gh0 + r) << 6) + gw0 + c) * 32 + nh * 8 + f;
        *(uint4*)&sK[px * SKSN + f * 4] = gk4[goff];
        *(uint4*)&sV[px * SKSN + f * 4] = gv4[goff];
    }
    // Zero pad rows 196..199
    for (int i = tid; i < (NPAD - NPX) * SKSN; i += 128) {
        sK[NPX * SKSN + i] = 0;
        sV[NPX * SKSN + i] = 0;
    }
    __syncthreads();

    // This warp's queries: rows grp -> (hA, wq), grp+8 -> (hB, wq)
    const int hA = h0 + wid * 2;
    const int hB = hA + 1;
    const int wq = w0 + grp;
    const int pixA = bbase + (hA << 6) + wq;
    const int pixB = pixA + 64;

    // Q fragments (pre-tf32, pre-scaled)
    unsigned qa[4][4];
    #pragma unroll
    for (int kc = 0; kc < 4; ++kc) {
        const int d = kc * 8 + tig;
        qa[kc][0] = g_q[pixA * CC + nh * 32 + d];
        qa[kc][1] = g_q[pixB * CC + nh * 32 + d];
        qa[kc][2] = g_q[pixA * CC + nh * 32 + d + 4];
        qa[kc][3] = g_q[pixB * CC + nh * 32 + d + 4];
    }

    // Window bounds in halo coords
    int hsA = hA - 3; hsA = hsA < 0 ? 0 : (hsA > 57 ? 57 : hsA);
    int hsB = hB - 3; hsB = hsB < 0 ? 0 : (hsB > 57 ? 57 : hsB);
    int wsq = wq - 3; wsq = wsq < 0 ? 0 : (wsq > 57 ? 57 : wsq);
    const int rA0 = hsA - gh0, rA1 = rA0 + 6;
    const int rB0 = hsB - gh0, rB1 = rB0 + 6;
    const int cq0 = wsq - gw0, cq1 = cq0 + 6;
    const int dhA = gh0 - hA + 6;
    const int dhB = gh0 - hB + 6;
    const int dwq = gw0 - wq + 6;

    // Incremental halo coords for this lane's two columns (2*tig, 2*tig+1)
    int wc0 = 2 * tig,     hr0 = 0;
    int wc1 = 2 * tig + 1, hr1 = 0;

    const int src0 = grp * 4 + (tig >> 1);
    const bool odd = tig & 1;

    float lA = 0.f, lB = 0.f;
    float oacc[4][4] = {};

    #pragma unroll 5
    for (int i = 0; i < NCHUNK; ++i) {
        const int n0 = i * 8;

        // S chunk: 16 x 8
        float sacc[4] = {};
        #pragma unroll
        for (int kc = 0; kc < 4; ++kc) {
            unsigned b0 = sK[(n0 + grp) * SKSN + kc * 8 + tig];
            unsigned b1 = sK[(n0 + grp) * SKSN + kc * 8 + tig + 4];
            mma_tf32(sacc, qa[kc][0], qa[kc][1], qa[kc][2], qa[kc][3], b0, b1);
        }

        // mask + bias + exp (transient)
        const bool vc0 = (wc0 >= cq0) & (wc0 <= cq1);
        const bool vc1 = (wc1 >= cq0) & (wc1 <= cq1);
        float e0 = (vc0 & (hr0 >= rA0) & (hr0 <= rA1))
                 ? __expf(sacc[0] + srp[(dhA + hr0) * 13 + dwq + wc0]) : 0.f;
        float e1 = (vc1 & (hr1 >= rA0) & (hr1 <= rA1))
                 ? __expf(sacc[1] + srp[(dhA + hr1) * 13 + dwq + wc1]) : 0.f;
        float e2 = (vc0 & (hr0 >= rB0) & (hr0 <= rB1))
                 ? __expf(sacc[2] + srp[(dhB + hr0) * 13 + dwq + wc0]) : 0.f;
        float e3 = (vc1 & (hr1 >= rB0) & (hr1 <= rB1))
                 ? __expf(sacc[3] + srp[(dhB + hr1) * 13 + dwq + wc1]) : 0.f;
        lA += e0 + e1;
        lB += e2 + e3;

        // Relayout accum->A fragment via shfl
        float p0a = __shfl_sync(0xffffffffu, e0, src0);
        float p0b = __shfl_sync(0xffffffffu, e1, src0);
        float p1a = __shfl_sync(0xffffffffu, e2, src0);
        float p1b = __shfl_sync(0xffffffffu, e3, src0);
        float p2a = __shfl_sync(0xffffffffu, e0, src0 + 2);
        float p2b = __shfl_sync(0xffffffffu, e1, src0 + 2);
        float p3a = __shfl_sync(0xffffffffu, e2, src0 + 2);
        float p3b = __shfl_sync(0xffffffffu, e3, src0 + 2);
        unsigned a0 = f2tf(odd ? p0b : p0a);
        unsigned a1 = f2tf(odd ? p1b : p1a);
        unsigned a2 = f2tf(odd ? p2b : p2a);
        unsigned a3 = f2tf(odd ? p3b : p3a);

        // P @ V chunk
        #pragma unroll
        for (int dt = 0; dt < 4; ++dt) {
            unsigned b0 = sV[(n0 + tig) * SKSN + dt * 8 + grp];
            unsigned b1 = sV[(n0 + tig + 4) * SKSN + dt * 8 + grp];
            mma_tf32(oacc[dt], a0, a1, a2, a3, b0, b1);
        }

        // advance halo coords by 8 columns
        wc0 += 8; if (wc0 >= NHALO_HW) { wc0 -= NHALO_HW; ++hr0; }
        wc1 += 8; if (wc1 >= NHALO_HW) { wc1 -= NHALO_HW; ++hr1; }
    }

    // Row sums across the 4 tig lanes (butterfly -> all lanes)
    lA += __shfl_xor_sync(0xffffffffu, lA, 1);
    lA += __shfl_xor_sync(0xffffffffu, lA, 2);
    lB += __shfl_xor_sync(0xffffffffu, lB, 1);
    lB += __shfl_xor_sync(0xffffffffu, lB, 2);
    const float invA = 1.f / lA;
    const float invB = 1.f / lB;

    #pragma unroll
    for (int dt = 0; dt < 4; ++dt) {
        const int dc = dt * 8 + tig * 2;
        *(float2*)&g_att[pixA * CC + nh * 32 + dc] =
            make_float2(oacc[dt][0] * invA, oacc[dt][1] * invA);
        *(float2*)&g_att[pixB * CC + nh * 32 + dc] =
            make_float2(oacc[dt][2] * invB, oacc[dt][3] * invB);
    }
}

extern "C" void kernel_launch(void* const* d_in, const int* in_sizes, int n_in,
                              void* d_out, int out_size) {
    (void)in_sizes; (void)n_in; (void)out_size;
    const float* x      = (const float*)d_in[0];
    const float* w_qkv  = (const float*)d_in[1];
    const float* b_qkv  = (const float*)d_in[2];
    const float* rpb    = (const float*)d_in[3];
    const float* w_proj = (const float*)d_in[4];
    const float* b_proj = (const float*)d_in[5];
    float* out = (float*)d_out;

    cudaFuncSetAttribute(natten_tc, cudaFuncAttributeMaxDynamicSharedMemorySize,
                         NATTEN_DSM);

    dim3 g1(MROWS / 64, 384 / 64);
    gemm_tc<384, 0><<<g1, 128>>>(x, w_qkv, b_qkv, nullptr);

    dim3 gn(WW / TTW, HH / TTH, BB * NHEAD);   // (8, 8, 8)
    natten_tc<<<gn, 128, NATTEN_DSM>>>(rpb);

    dim3 g2(MROWS / 64, 128 / 64);
    gemm_tc<128, 1><<<g2, 128>>>(nullptr, w_proj, b_proj, out);
}

// round 10
// speedup vs baseline: 1.3029x; 1.3029x over previous
#include <cuda_runtime.h>

#define BB 2
#define HH 64
#define WW 64
#define CC 128
#define NHEAD 4
#define HD 32
#define KWIN 7
#define MROWS (BB*HH*WW)          /* 8192 */
#define SCALE 0.17677669529663687f /* 32^-0.5 */

// Scratch (allocation-free rule: device globals).
// q/k/v hold tf32 bit patterns (written by GEMM epilogue); att is fp32.
__device__ unsigned g_q[MROWS*CC];
__device__ unsigned g_k[MROWS*CC];
__device__ unsigned g_v[MROWS*CC];
__device__ float    g_att[MROWS*CC];

__device__ __forceinline__ unsigned f2tf(float f) {
    unsigned r;
    asm("cvt.rna.tf32.f32 %0, %1;" : "=r"(r) : "f"(f));
    return r;
}

__device__ __forceinline__ void mma_tf32(float c[4],
    unsigned a0, unsigned a1, unsigned a2, unsigned a3,
    unsigned b0, unsigned b1) {
    asm volatile(
        "mma.sync.aligned.m16n8k8.row.col.f32.tf32.tf32.f32 "
        "{%0,%1,%2,%3}, {%4,%5,%6,%7}, {%8,%9}, {%0,%1,%2,%3};"
        : "+f"(c[0]), "+f"(c[1]), "+f"(c[2]), "+f"(c[3])
        : "r"(a0), "r"(a1), "r"(a2), "r"(a3), "r"(b0), "r"(b1));
}

// ---------------------------------------------------------------------------
// tf32 tensor-core GEMM (Round-6/8 version — measured best: 14.3us QKV).
// Block tile 128x64, 256 threads = 8 warps (4M x 2N), warp tile 32x32.
// MODE 0 epilogue writes q/k/v as tf32 bit patterns.
// ---------------------------------------------------------------------------
template<int NTOT, int MODE>
__global__ __launch_bounds__(256)
void gemm_tc(const float* __restrict__ A,
             const float* __restrict__ W,
             const float* __restrict__ bias,
             float* __restrict__ out) {
    __shared__ __align__(16) unsigned As[128 * 36];
    __shared__ __align__(16) unsigned Bs[32 * 72];

    const float* Ap = (MODE == 1) ? (const float*)g_att : A;

    const int tid  = threadIdx.x;
    const int lane = tid & 31;
    const int wid  = tid >> 5;
    const int warpM = wid & 3;
    const int warpN = wid >> 2;
    const int grp = lane >> 2;
    const int tig = lane & 3;
    const int rowbase = blockIdx.x * 128;
    const int colbase = blockIdx.y * 64;

    float acc[2][4][4] = {};

    for (int kc = 0; kc < 4; ++kc) {
        const int k0 = kc * 32;
        #pragma unroll
        for (int j = 0; j < 4; ++j) {
            const int i = tid + j * 256;
            const int m  = i >> 3;
            const int kq = (i & 7) * 4;
            float4 v = *(const float4*)&Ap[(rowbase + m) * 128 + k0 + kq];
            uint4 u = make_uint4(f2tf(v.x), f2tf(v.y), f2tf(v.z), f2tf(v.w));
            *(uint4*)&As[m * 36 + kq] = u;
        }
        #pragma unroll
        for (int j = 0; j < 2; ++j) {
            const int i = tid + j * 256;
            const int k  = i >> 4;
            const int nq = (i & 15) * 4;
            float4 v = *(const float4*)&W[(k0 + k) * NTOT + colbase + nq];
            uint4 u = make_uint4(f2tf(v.x), f2tf(v.y), f2tf(v.z), f2tf(v.w));
            *(uint4*)&Bs[k * 72 + nq] = u;
        }
        __syncthreads();

        #pragma unroll
        for (int ks = 0; ks < 4; ++ks) {
            const int kk = ks * 8;
            unsigned a[2][4], b[4][2];
            #pragma unroll
            for (int mf = 0; mf < 2; ++mf) {
                const int r = warpM * 32 + mf * 16 + grp;
                a[mf][0] = As[r * 36 + kk + tig];
                a[mf][1] = As[(r + 8) * 36 + kk + tig];
                a[mf][2] = As[r * 36 + kk + tig + 4];
                a[mf][3] = As[(r + 8) * 36 + kk + tig + 4];
            }
            #pragma unroll
            for (int nf = 0; nf < 4; ++nf) {
                const int c = warpN * 32 + nf * 8 + grp;
                b[nf][0] = Bs[(kk + tig) * 72 + c];
                b[nf][1] = Bs[(kk + tig + 4) * 72 + c];
            }
            #pragma unroll
            for (int mf = 0; mf < 2; ++mf)
                #pragma unroll
                for (int nf = 0; nf < 4; ++nf)
                    mma_tf32(acc[mf][nf],
                             a[mf][0], a[mf][1], a[mf][2], a[mf][3],
                             b[nf][0], b[nf][1]);
        }
        __syncthreads();
    }

    #pragma unroll
    for (int mf = 0; mf < 2; ++mf) {
        #pragma unroll
        for (int nf = 0; nf < 4; ++nf) {
            const int colL = colbase + warpN * 32 + nf * 8 + tig * 2;
            const float bs0 = bias[colL];
            const float bs1 = bias[colL + 1];
            #pragma unroll
            for (int rr = 0; rr < 2; ++rr) {
                const int row = rowbase + warpM * 32 + mf * 16 + grp + rr * 8;
                float v0 = acc[mf][nf][rr * 2 + 0] + bs0;
                float v1 = acc[mf][nf][rr * 2 + 1] + bs1;
                if (MODE == 0) {
                    const int comp  = colL >> 7;
                    const int inner = colL & 127;
                    if (comp == 0)
                        *(uint2*)&g_q[row * CC + inner] = make_uint2(f2tf(v0 * SCALE), f2tf(v1 * SCALE));
                    else if (comp == 1)
                        *(uint2*)&g_k[row * CC + inner] = make_uint2(f2tf(v0), f2tf(v1));
                    else
                        *(uint2*)&g_v[row * CC + inner] = make_uint2(f2tf(v0), f2tf(v1));
                } else {
                    *(float2*)&out[row * NTOT + colL] = make_float2(v0, v1);
                }
            }
        }
    }
}

// ---------------------------------------------------------------------------
// Neighborhood attention v5.1 (Round-8 structure; staging is now pure copies
// since K/V/Q are pre-converted to tf32 by the GEMM epilogue).
// Block = 4(h) x 8(w) pixel tile x 1 head = 32 queries, 2 m16-tiles.
// 4 warps = (m-tile, n-half). Halo 10x14=140 px (pad 144), stride 36.
// ---------------------------------------------------------------------------
#define TTH 4
#define TTW 8
#define NHALO_H 10
#define NHALO_W 14
#define NPX 140
#define NPAD 144
#define SKSN 36

__global__ __launch_bounds__(128)
void natten_tc(const float* __restrict__ rpb) {
    __shared__ __align__(16) unsigned sK[NPAD * SKSN];
    __shared__ __align__(16) unsigned sV[NPAD * SKSN];
    __shared__ float srp[169];
    __shared__ float sl[2][2][16];

    const int tid  = threadIdx.x;
    const int lane = tid & 31;
    const int wid  = tid >> 5;     // 0..3
    const int mt   = wid >> 1;     // m-tile (pixel rows mt*2, mt*2+1)
    const int half = wid & 1;      // n-half: cols [half*72, half*72+72)
    const int grp  = lane >> 2;    // 0..7
    const int tig  = lane & 3;     // 0..3

    const int w0 = blockIdx.x * TTW;
    const int h0 = blockIdx.y * TTH;
    const int nh = blockIdx.z & 3;
    const int b  = blockIdx.z >> 2;
    const int bbase = b << 12;

    int gh0 = h0 - 3; gh0 = gh0 < 0 ? 0 : (gh0 > 64 - NHALO_H ? 64 - NHALO_H : gh0);
    int gw0 = w0 - 3; gw0 = gw0 < 0 ? 0 : (gw0 > 64 - NHALO_W ? 64 - NHALO_W : gw0);

    for (int i = tid; i < 169; i += 128) srp[i] = rpb[nh * 169 + i];

    // Stage K/V halo (pre-tf32) — pure uint4 copies
    const uint4* gk4 = (const uint4*)g_k;
    const uint4* gv4 = (const uint4*)g_v;
    for (int i = tid; i < NPX * 8; i += 128) {
        const int px = i >> 3;
        const int f  = i & 7;
        const int r  = px / NHALO_W;
        const int c  = px - r * NHALO_W;
        const int goff = (bbase + ((gh0 + r) << 6) + gw0 + c) * 32 + nh * 8 + f;
        *(uint4*)&sK[px * SKSN + f * 4] = gk4[goff];
        *(uint4*)&sV[px * SKSN + f * 4] = gv4[goff];
    }
    // Zero pad rows 140..143 (sV mandatory: 0 * garbage must stay 0)
    for (int i = tid; i < (NPAD - NPX) * SKSN; i += 128) {
        sK[NPX * SKSN + i] = 0;
        sV[NPX * SKSN + i] = 0;
    }
    __syncthreads();

    // Query pixels for this warp's m-tile: rows grp (pixA) and grp+8 (pixB)
    const int hA = h0 + mt * 2;
    const int hB = hA + 1;
    const int wq = w0 + grp;
    const int pixA = bbase + (hA << 6) + wq;
    const int pixB = pixA + 64;

    // Q A-fragments (pre-tf32, pre-scaled)
    unsigned qa[4][4];
    #pragma unroll
    for (int kc = 0; kc < 4; ++kc) {
        const int d = kc * 8 + tig;
        qa[kc][0] = g_q[pixA * CC + nh * 32 + d];
        qa[kc][1] = g_q[pixB * CC + nh * 32 + d];
        qa[kc][2] = g_q[pixA * CC + nh * 32 + d + 4];
        qa[kc][3] = g_q[pixB * CC + nh * 32 + d + 4];
    }

    // S = Q @ K^T over this warp's 72 neighbor columns
    float sacc[9][4] = {};
    #pragma unroll
    for (int i = 0; i < 9; ++i) {
        const int n0 = half * 72 + i * 8;
        #pragma unroll
        for (int kc = 0; kc < 4; ++kc) {
            unsigned b0 = sK[(n0 + grp) * SKSN + kc * 8 + tig];
            unsigned b1 = sK[(n0 + grp) * SKSN + kc * 8 + tig + 4];
            mma_tf32(sacc[i], qa[kc][0], qa[kc][1], qa[kc][2], qa[kc][3], b0, b1);
        }
    }

    // Mask + bias + exp
    int hsA = hA - 3; hsA = hsA < 0 ? 0 : (hsA > 57 ? 57 : hsA);
    int hsB = hB - 3; hsB = hsB < 0 ? 0 : (hsB > 57 ? 57 : hsB);
    int wsq = wq - 3; wsq = wsq < 0 ? 0 : (wsq > 57 ? 57 : wsq);

    float e[9][4];
    float lA = 0.f, lB = 0.f;
    #pragma unroll
    for (int i = 0; i < 9; ++i) {
        #pragma unroll
        for (int ee = 0; ee < 2; ++ee) {
            const int n  = half * 72 + i * 8 + 2 * tig + ee;
            const int hr = n / NHALO_W;
            const int wc = n - hr * NHALO_W;
            const int kh = gh0 + hr;
            const int kw = gw0 + wc;
            const bool vw = (kw >= wsq) && (kw <= wsq + 6);
            float eA = 0.f, eB = 0.f;
            if (vw && kh >= hsA && kh <= hsA + 6)
                eA = __expf(sacc[i][ee]     + srp[(kh - hA + 6) * 13 + (kw - wq + 6)]);
            if (vw && kh >= hsB && kh <= hsB + 6)
                eB = __expf(sacc[i][2 + ee] + srp[(kh - hB + 6) * 13 + (kw - wq + 6)]);
            e[i][ee]     = eA;
            e[i][2 + ee] = eB;
            lA += eA;
            lB += eB;
        }
    }
    lA += __shfl_xor_sync(0xffffffffu, lA, 1);
    lA += __shfl_xor_sync(0xffffffffu, lA, 2);
    lB += __shfl_xor_sync(0xffffffffu, lB, 1);
    lB += __shfl_xor_sync(0xffffffffu, lB, 2);
    if (tig == 0) {
        sl[mt][half][grp]     = lA;
        sl[mt][half][grp + 8] = lB;
    }
    __syncthreads();
    const float invA = 1.f / (sl[mt][0][grp]     + sl[mt][1][grp]);
    const float invB = 1.f / (sl[mt][0][grp + 8] + sl[mt][1][grp + 8]);

    // O = P @ V over this warp's 72 neighbors
    float oacc[4][4] = {};
    const int src0 = grp * 4 + (tig >> 1);
    const bool odd = tig & 1;
    #pragma unroll
    for (int i = 0; i < 9; ++i) {
        float p0a = __shfl_sync(0xffffffffu, e[i][0], src0);
        float p0b = __shfl_sync(0xffffffffu, e[i][1], src0);
        float p1a = __shfl_sync(0xffffffffu, e[i][2], src0);
        float p1b = __shfl_sync(0xffffffffu, e[i][3], src0);
        float p2a = __shfl_sync(0xffffffffu, e[i][0], src0 + 2);
        float p2b = __shfl_sync(0xffffffffu, e[i][1], src0 + 2);
        float p3a = __shfl_sync(0xffffffffu, e[i][2], src0 + 2);
        float p3b = __shfl_sync(0xffffffffu, e[i][3], src0 + 2);
        unsigned a0 = f2tf(odd ? p0b : p0a);
        unsigned a1 = f2tf(odd ? p1b : p1a);
        unsigned a2 = f2tf(odd ? p2b : p2a);
        unsigned a3 = f2tf(odd ? p3b : p3a);
        const int kb = half * 72 + i * 8;
        #pragma unroll
        for (int dt = 0; dt < 4; ++dt) {
            unsigned b0 = sV[(kb + tig) * SKSN + dt * 8 + grp];
            unsigned b1 = sV[(kb + tig + 4) * SKSN + dt * 8 + grp];
            mma_tf32(oacc[dt], a0, a1, a2, a3, b0, b1);
        }
    }

    // Combine the two n-halves per m-tile via smem
    __shared__ __align__(16) float sO[2][16 * 32];
    #pragma unroll
    for (int dt = 0; dt < 4; ++dt) {
        const int dc = dt * 8 + tig * 2;
        if (half == 0) {
            sO[mt][grp * 32 + dc]            = oacc[dt][0];
            sO[mt][grp * 32 + dc + 1]        = oacc[dt][1];
            sO[mt][(grp + 8) * 32 + dc]      = oacc[dt][2];
            sO[mt][(grp + 8) * 32 + dc + 1]  = oacc[dt][3];
        }
    }
    __syncthreads();
    if (half == 1) {
        #pragma unroll
        for (int dt = 0; dt < 4; ++dt) {
            const int dc = dt * 8 + tig * 2;
            float t0 = oacc[dt][0] + sO[mt][grp * 32 + dc];
            float t1 = oacc[dt][1] + sO[mt][grp * 32 + dc + 1];
            float t2 = oacc[dt][2] + sO[mt][(grp + 8) * 32 + dc];
            float t3 = oacc[dt][3] + sO[mt][(grp + 8) * 32 + dc + 1];
            *(float2*)&g_att[pixA * CC + nh * 32 + dc] = make_float2(t0 * invA, t1 * invA);
            *(float2*)&g_att[pixB * CC + nh * 32 + dc] = make_float2(t2 * invB, t3 * invB);
        }
    }
}

extern "C" void kernel_launch(void* const* d_in, const int* in_sizes, int n_in,
                              void* d_out, int out_size) {
    (void)in_sizes; (void)n_in; (void)out_size;
    const float* x      = (const float*)d_in[0];
    const float* w_qkv  = (const float*)d_in[1];
    const float* b_qkv  = (const float*)d_in[2];
    const float* rpb    = (const float*)d_in[3];
    const float* w_proj = (const float*)d_in[4];
    const float* b_proj = (const float*)d_in[5];
    float* out = (float*)d_out;

    dim3 g1(MROWS / 128, 384 / 64);
    gemm_tc<384, 0><<<g1, 256>>>(x, w_qkv, b_qkv, nullptr);

    dim3 gn(WW / TTW, HH / TTH, BB * NHEAD);   // (8, 16, 8)
    natten_tc<<<gn, 128>>>(rpb);

    dim3 g2(MROWS / 128, 128 / 64);
    gemm_tc<128, 1><<<g2, 256>>>(nullptr, w_proj, b_proj, out);
}

// round 11
// speedup vs baseline: 1.3158x; 1.0099x over previous
#include <cuda_runtime.h>

#define BB 2
#define HH 64
#define WW 64
#define CC 128
#define NHEAD 4
#define HD 32
#define KWIN 7
#define MROWS (BB*HH*WW)          /* 8192 */
#define SCALE 0.17677669529663687f /* 32^-0.5 */

// Scratch (allocation-free rule: device globals).
// q/k/v hold tf32 bit patterns (written by GEMM epilogue); att is fp32.
__device__ unsigned g_q[MROWS*CC];
__device__ unsigned g_k[MROWS*CC];
__device__ unsigned g_v[MROWS*CC];
__device__ float    g_att[MROWS*CC];

__device__ __forceinline__ unsigned f2tf(float f) {
    unsigned r;
    asm("cvt.rna.tf32.f32 %0, %1;" : "=r"(r) : "f"(f));
    return r;
}

__device__ __forceinline__ void mma_tf32(float c[4],
    unsigned a0, unsigned a1, unsigned a2, unsigned a3,
    unsigned b0, unsigned b1) {
    asm volatile(
        "mma.sync.aligned.m16n8k8.row.col.f32.tf32.tf32.f32 "
        "{%0,%1,%2,%3}, {%4,%5,%6,%7}, {%8,%9}, {%0,%1,%2,%3};"
        : "+f"(c[0]), "+f"(c[1]), "+f"(c[2]), "+f"(c[3])
        : "r"(a0), "r"(a1), "r"(a2), "r"(a3), "r"(b0), "r"(b1));
}

// ---------------------------------------------------------------------------
// tf32 tensor-core GEMM (Round-8/10 version — measured best; UNCHANGED).
// Block tile 128x64, 256 threads = 8 warps (4M x 2N), warp tile 32x32.
// MODE 0 epilogue writes q/k/v as tf32 bit patterns.
// ---------------------------------------------------------------------------
template<int NTOT, int MODE>
__global__ __launch_bounds__(256)
void gemm_tc(const float* __restrict__ A,
             const float* __restrict__ W,
             const float* __restrict__ bias,
             float* __restrict__ out) {
    __shared__ __align__(16) unsigned As[128 * 36];
    __shared__ __align__(16) unsigned Bs[32 * 72];

    const float* Ap = (MODE == 1) ? (const float*)g_att : A;

    const int tid  = threadIdx.x;
    const int lane = tid & 31;
    const int wid  = tid >> 5;
    const int warpM = wid & 3;
    const int warpN = wid >> 2;
    const int grp = lane >> 2;
    const int tig = lane & 3;
    const int rowbase = blockIdx.x * 128;
    const int colbase = blockIdx.y * 64;

    float acc[2][4][4] = {};

    for (int kc = 0; kc < 4; ++kc) {
        const int k0 = kc * 32;
        #pragma unroll
        for (int j = 0; j < 4; ++j) {
            const int i = tid + j * 256;
            const int m  = i >> 3;
            const int kq = (i & 7) * 4;
            float4 v = *(const float4*)&Ap[(rowbase + m) * 128 + k0 + kq];
            uint4 u = make_uint4(f2tf(v.x), f2tf(v.y), f2tf(v.z), f2tf(v.w));
            *(uint4*)&As[m * 36 + kq] = u;
        }
        #pragma unroll
        for (int j = 0; j < 2; ++j) {
            const int i = tid + j * 256;
            const int k  = i >> 4;
            const int nq = (i & 15) * 4;
            float4 v = *(const float4*)&W[(k0 + k) * NTOT + colbase + nq];
            uint4 u = make_uint4(f2tf(v.x), f2tf(v.y), f2tf(v.z), f2tf(v.w));
            *(uint4*)&Bs[k * 72 + nq] = u;
        }
        __syncthreads();

        #pragma unroll
        for (int ks = 0; ks < 4; ++ks) {
            const int kk = ks * 8;
            unsigned a[2][4], b[4][2];
            #pragma unroll
            for (int mf = 0; mf < 2; ++mf) {
                const int r = warpM * 32 + mf * 16 + grp;
                a[mf][0] = As[r * 36 + kk + tig];
                a[mf][1] = As[(r + 8) * 36 + kk + tig];
                a[mf][2] = As[r * 36 + kk + tig + 4];
                a[mf][3] = As[(r + 8) * 36 + kk + tig + 4];
            }
            #pragma unroll
            for (int nf = 0; nf < 4; ++nf) {
                const int c = warpN * 32 + nf * 8 + grp;
                b[nf][0] = Bs[(kk + tig) * 72 + c];
                b[nf][1] = Bs[(kk + tig + 4) * 72 + c];
            }
            #pragma unroll
            for (int mf = 0; mf < 2; ++mf)
                #pragma unroll
                for (int nf = 0; nf < 4; ++nf)
                    mma_tf32(acc[mf][nf],
                             a[mf][0], a[mf][1], a[mf][2], a[mf][3],
                             b[nf][0], b[nf][1]);
        }
        __syncthreads();
    }

    #pragma unroll
    for (int mf = 0; mf < 2; ++mf) {
        #pragma unroll
        for (int nf = 0; nf < 4; ++nf) {
            const int colL = colbase + warpN * 32 + nf * 8 + tig * 2;
            const float bs0 = bias[colL];
            const float bs1 = bias[colL + 1];
            #pragma unroll
            for (int rr = 0; rr < 2; ++rr) {
                const int row = rowbase + warpM * 32 + mf * 16 + grp + rr * 8;
                float v0 = acc[mf][nf][rr * 2 + 0] + bs0;
                float v1 = acc[mf][nf][rr * 2 + 1] + bs1;
                if (MODE == 0) {
                    const int comp  = colL >> 7;
                    const int inner = colL & 127;
                    if (comp == 0)
                        *(uint2*)&g_q[row * CC + inner] = make_uint2(f2tf(v0 * SCALE), f2tf(v1 * SCALE));
                    else if (comp == 1)
                        *(uint2*)&g_k[row * CC + inner] = make_uint2(f2tf(v0), f2tf(v1));
                    else
                        *(uint2*)&g_v[row * CC + inner] = make_uint2(f2tf(v0), f2tf(v1));
                } else {
                    *(float2*)&out[row * NTOT + colL] = make_float2(v0, v1);
                }
            }
        }
    }
}

// ---------------------------------------------------------------------------
// Neighborhood attention v5.2 (Round-10 structure + two residency/latency
// fixes: (a) sO aliased into sK's smem (sK dead after S-phase; sO written
// only after the sl barrier, by which point all S-mma reads are done) ->
// ~42.4KB static smem -> 5 resident blocks/SM (was 4);
// (b) Q fragment LDGs hoisted above halo staging to overlap gmem latency.
// ---------------------------------------------------------------------------
#define TTH 4
#define TTW 8
#define NHALO_H 10
#define NHALO_W 14
#define NPX 140
#define NPAD 144
#define SKSN 36

__global__ __launch_bounds__(128)
void natten_tc(const float* __restrict__ rpb) {
    __shared__ __align__(16) unsigned sK[NPAD * SKSN];
    __shared__ __align__(16) unsigned sV[NPAD * SKSN];
    __shared__ float srp[169];
    __shared__ float sl[2][2][16];

    // sO aliases the front of sK (4KB of 20.7KB). Safe: all sK reads happen
    // before the sl __syncthreads(); all sO accesses happen after it.
    float* sO = (float*)sK;   // layout: sO[mt*512 + row*32 + col]

    const int tid  = threadIdx.x;
    const int lane = tid & 31;
    const int wid  = tid >> 5;     // 0..3
    const int mt   = wid >> 1;     // m-tile (pixel rows mt*2, mt*2+1)
    const int half = wid & 1;      // n-half: cols [half*72, half*72+72)
    const int grp  = lane >> 2;    // 0..7
    const int tig  = lane & 3;     // 0..3

    const int w0 = blockIdx.x * TTW;
    const int h0 = blockIdx.y * TTH;
    const int nh = blockIdx.z & 3;
    const int b  = blockIdx.z >> 2;
    const int bbase = b << 12;

    int gh0 = h0 - 3; gh0 = gh0 < 0 ? 0 : (gh0 > 64 - NHALO_H ? 64 - NHALO_H : gh0);
    int gw0 = w0 - 3; gw0 = gw0 < 0 ? 0 : (gw0 > 64 - NHALO_W ? 64 - NHALO_W : gw0);

    // Query pixels for this warp's m-tile: rows grp (pixA) and grp+8 (pixB)
    const int hA = h0 + mt * 2;
    const int hB = hA + 1;
    const int wq = w0 + grp;
    const int pixA = bbase + (hA << 6) + wq;
    const int pixB = pixA + 64;

    // Q A-fragments (pre-tf32, pre-scaled) — issued BEFORE staging so the
    // LDG latency overlaps the halo copy.
    unsigned qa[4][4];
    #pragma unroll
    for (int kc = 0; kc < 4; ++kc) {
        const int d = kc * 8 + tig;
        qa[kc][0] = g_q[pixA * CC + nh * 32 + d];
        qa[kc][1] = g_q[pixB * CC + nh * 32 + d];
        qa[kc][2] = g_q[pixA * CC + nh * 32 + d + 4];
        qa[kc][3] = g_q[pixB * CC + nh * 32 + d + 4];
    }

    for (int i = tid; i < 169; i += 128) srp[i] = rpb[nh * 169 + i];

    // Stage K/V halo (pre-tf32) — pure uint4 copies
    const uint4* gk4 = (const uint4*)g_k;
    const uint4* gv4 = (const uint4*)g_v;
    for (int i = tid; i < NPX * 8; i += 128) {
        const int px = i >> 3;
        const int f  = i & 7;
        const int r  = px / NHALO_W;
        const int c  = px - r * NHALO_W;
        const int goff = (bbase + ((gh0 + r) << 6) + gw0 + c) * 32 + nh * 8 + f;
        *(uint4*)&sK[px * SKSN + f * 4] = gk4[goff];
        *(uint4*)&sV[px * SKSN + f * 4] = gv4[goff];
    }
    // Zero pad rows 140..143 (sV mandatory: 0 * garbage must stay 0)
    for (int i = tid; i < (NPAD - NPX) * SKSN; i += 128) {
        sK[NPX * SKSN + i] = 0;
        sV[NPX * SKSN + i] = 0;
    }
    __syncthreads();

    // S = Q @ K^T over this warp's 72 neighbor columns
    float sacc[9][4] = {};
    #pragma unroll
    for (int i = 0; i < 9; ++i) {
        const int n0 = half * 72 + i * 8;
        #pragma unroll
        for (int kc = 0; kc < 4; ++kc) {
            unsigned b0 = sK[(n0 + grp) * SKSN + kc * 8 + tig];
            unsigned b1 = sK[(n0 + grp) * SKSN + kc * 8 + tig + 4];
            mma_tf32(sacc[i], qa[kc][0], qa[kc][1], qa[kc][2], qa[kc][3], b0, b1);
        }
    }

    // Mask + bias + exp
    int hsA = hA - 3; hsA = hsA < 0 ? 0 : (hsA > 57 ? 57 : hsA);
    int hsB = hB - 3; hsB = hsB < 0 ? 0 : (hsB > 57 ? 57 : hsB);
    int wsq = wq - 3; wsq = wsq < 0 ? 0 : (wsq > 57 ? 57 : wsq);

    float e[9][4];
    float lA = 0.f, lB = 0.f;
    #pragma unroll
    for (int i = 0; i < 9; ++i) {
        #pragma unroll
        for (int ee = 0; ee < 2; ++ee) {
            const int n  = half * 72 + i * 8 + 2 * tig + ee;
            const int hr = n / NHALO_W;
            const int wc = n - hr * NHALO_W;
            const int kh = gh0 + hr;
            const int kw = gw0 + wc;
            const bool vw = (kw >= wsq) && (kw <= wsq + 6);
            float eA = 0.f, eB = 0.f;
            if (vw && kh >= hsA && kh <= hsA + 6)
                eA = __expf(sacc[i][ee]     + srp[(kh - hA + 6) * 13 + (kw - wq + 6)]);
            if (vw && kh >= hsB && kh <= hsB + 6)
                eB = __expf(sacc[i][2 + ee] + srp[(kh - hB + 6) * 13 + (kw - wq + 6)]);
            e[i][ee]     = eA;
            e[i][2 + ee] = eB;
            lA += eA;
            lB += eB;
        }
    }
    lA += __shfl_xor_sync(0xffffffffu, lA, 1);
    lA += __shfl_xor_sync(0xffffffffu, lA, 2);
    lB += __shfl_xor_sync(0xffffffffu, lB, 1);
    lB += __shfl_xor_sync(0xffffffffu, lB, 2);
    if (tig == 0) {
        sl[mt][half][grp]     = lA;
        sl[mt][half][grp + 8] = lB;
    }
    __syncthreads();   // after this barrier, sK is dead -> sO may use it
    const float invA = 1.f / (sl[mt][0][grp]     + sl[mt][1][grp]);
    const float invB = 1.f / (sl[mt][0][grp + 8] + sl[mt][1][grp + 8]);

    // O = P @ V over this warp's 72 neighbors
    float oacc[4][4] = {};
    const int src0 = grp * 4 + (tig >> 1);
    const bool odd = tig & 1;
    #pragma unroll
    for (int i = 0; i < 9; ++i) {
        float p0a = __shfl_sync(0xffffffffu, e[i][0], src0);
        float p0b = __shfl_sync(0xffffffffu, e[i][1], src0);
        float p1a = __shfl_sync(0xffffffffu, e[i][2], src0);
        float p1b = __shfl_sync(0xffffffffu, e[i][3], src0);
        float p2a = __shfl_sync(0xffffffffu, e[i][0], src0 + 2);
        float p2b = __shfl_sync(0xffffffffu, e[i][1], src0 + 2);
        float p3a = __shfl_sync(0xffffffffu, e[i][2], src0 + 2);
        float p3b = __shfl_sync(0xffffffffu, e[i][3], src0 + 2);
        unsigned a0 = f2tf(odd ? p0b : p0a);
        unsigned a1 = f2tf(odd ? p1b : p1a);
        unsigned a2 = f2tf(odd ? p2b : p2a);
        unsigned a3 = f2tf(odd ? p3b : p3a);
        const int kb = half * 72 + i * 8;
        #pragma unroll
        for (int dt = 0; dt < 4; ++dt) {
            unsigned b0 = sV[(kb + tig) * SKSN + dt * 8 + grp];
            unsigned b1 = sV[(kb + tig + 4) * SKSN + dt * 8 + grp];
            mma_tf32(oacc[dt], a0, a1, a2, a3, b0, b1);
        }
    }

    // Combine the two n-halves per m-tile via the aliased sO region
    #pragma unroll
    for (int dt = 0; dt < 4; ++dt) {
        const int dc = dt * 8 + tig * 2;
        if (half == 0) {
            sO[mt * 512 + grp * 32 + dc]            = oacc[dt][0];
            sO[mt * 512 + grp * 32 + dc + 1]        = oacc[dt][1];
            sO[mt * 512 + (grp + 8) * 32 + dc]      = oacc[dt][2];
            sO[mt * 512 + (grp + 8) * 32 + dc + 1]  = oacc[dt][3];
        }
    }
    __syncthreads();
    if (half == 1) {
        #pragma unroll
        for (int dt = 0; dt < 4; ++dt) {
            const int dc = dt * 8 + tig * 2;
            float t0 = oacc[dt][0] + sO[mt * 512 + grp * 32 + dc];
            float t1 = oacc[dt][1] + sO[mt * 512 + grp * 32 + dc + 1];
            float t2 = oacc[dt][2] + sO[mt * 512 + (grp + 8) * 32 + dc];
            float t3 = oacc[dt][3] + sO[mt * 512 + (grp + 8) * 32 + dc + 1];
            *(float2*)&g_att[pixA * CC + nh * 32 + dc] = make_float2(t0 * invA, t1 * invA);
            *(float2*)&g_att[pixB * CC + nh * 32 + dc] = make_float2(t2 * invB, t3 * invB);
        }
    }
}

extern "C" void kernel_launch(void* const* d_in, const int* in_sizes, int n_in,
                              void* d_out, int out_size) {
    (void)in_sizes; (void)n_in; (void)out_size;
    const float* x      = (const float*)d_in[0];
    const float* w_qkv  = (const float*)d_in[1];
    const float* b_qkv  = (const float*)d_in[2];
    const float* rpb    = (const float*)d_in[3];
    const float* w_proj = (const float*)d_in[4];
    const float* b_proj = (const float*)d_in[5];
    float* out = (float*)d_out;

    dim3 g1(MROWS / 128, 384 / 64);
    gemm_tc<384, 0><<<g1, 256>>>(x, w_qkv, b_qkv, nullptr);

    dim3 gn(WW / TTW, HH / TTH, BB * NHEAD);   // (8, 16, 8)
    natten_tc<<<gn, 128>>>(rpb);

    dim3 g2(MROWS / 128, 128 / 64);
    gemm_tc<128, 1><<<g2, 256>>>(nullptr, w_proj, b_proj, out);
}